// round 2
// baseline (speedup 1.0000x reference)
#include <cuda_runtime.h>
#include <math.h>

#define LSEQ 8192
#define EDIM 1024
#define NH   16
#define HD   64
#define CH   64
#define NW   (LSEQ/CH)

// Scratch (allocation-free rule: __device__ globals)
__device__ float g_q  [(size_t)LSEQ*EDIM];
__device__ float g_k  [(size_t)LSEQ*EDIM];
__device__ float g_v  [(size_t)LSEQ*EDIM];
__device__ float g_att[(size_t)LSEQ*EDIM];
__device__ float g_nrm[(size_t)LSEQ*EDIM];

// ---- packed f32x2 helpers (sm_100+; b64 registers as 2xf32 carriers) ----
typedef unsigned long long u64;
__device__ __forceinline__ u64 pk2(float x) {
    u64 d; asm("mov.b64 %0, {%1, %1};" : "=l"(d) : "f"(x)); return d;
}
__device__ __forceinline__ u64 ffma2(u64 a, u64 b, u64 c) {
    u64 d; asm("fma.rn.f32x2 %0, %1, %2, %3;" : "=l"(d) : "l"(a), "l"(b), "l"(c));
    return d;
}

// ============================================================================
// GEMM: C[m][n] = alpha * (sum_k A[m][k]*B[n][k] + bias[n])
// A: MxK row-major, B: NxK row-major (i.e. computes A @ B^T), C: MxN.
// 128x128 block tile, BK=16, 8x8 per-thread microtile, f32x2 packed math.
// ============================================================================
__global__ __launch_bounds__(256)
void gemm_abt(const float* __restrict__ A, const float* __restrict__ B,
              const float* __restrict__ bias, float* __restrict__ C,
              int M, int N, int K, float alpha)
{
    __shared__ float As[16][128];
    __shared__ float Bs[16][128];
    const int tid  = threadIdx.x;
    const int m0   = blockIdx.y * 128;
    const int n0   = blockIdx.x * 128;
    const int trow = tid >> 4;   // 0..15
    const int tcol = tid & 15;   // 0..15

    u64 acc[8][4];
    #pragma unroll
    for (int i = 0; i < 8; i++)
        #pragma unroll
        for (int j = 0; j < 4; j++) acc[i][j] = 0ull;

    const int r  = tid >> 2;          // 0..63
    const int c4 = (tid & 3) << 2;    // 0,4,8,12

    for (int k0 = 0; k0 < K; k0 += 16) {
        float4 ta0 = *(const float4*)(A + (size_t)(m0 + r     ) * K + k0 + c4);
        float4 ta1 = *(const float4*)(A + (size_t)(m0 + r + 64) * K + k0 + c4);
        float4 tb0 = *(const float4*)(B + (size_t)(n0 + r     ) * K + k0 + c4);
        float4 tb1 = *(const float4*)(B + (size_t)(n0 + r + 64) * K + k0 + c4);
        As[c4+0][r]    = ta0.x; As[c4+1][r]    = ta0.y; As[c4+2][r]    = ta0.z; As[c4+3][r]    = ta0.w;
        As[c4+0][r+64] = ta1.x; As[c4+1][r+64] = ta1.y; As[c4+2][r+64] = ta1.z; As[c4+3][r+64] = ta1.w;
        Bs[c4+0][r]    = tb0.x; Bs[c4+1][r]    = tb0.y; Bs[c4+2][r]    = tb0.z; Bs[c4+3][r]    = tb0.w;
        Bs[c4+0][r+64] = tb1.x; Bs[c4+1][r+64] = tb1.y; Bs[c4+2][r+64] = tb1.z; Bs[c4+3][r+64] = tb1.w;
        __syncthreads();

        #pragma unroll
        for (int kk = 0; kk < 16; kk++) {
            float ra[8];
            *(float4*)&ra[0] = *(const float4*)&As[kk][trow*8];
            *(float4*)&ra[4] = *(const float4*)&As[kk][trow*8 + 4];
            u64 rb[4];
            *(ulonglong2*)&rb[0] = *(const ulonglong2*)&Bs[kk][tcol*8];
            *(ulonglong2*)&rb[2] = *(const ulonglong2*)&Bs[kk][tcol*8 + 4];
            #pragma unroll
            for (int i = 0; i < 8; i++) {
                u64 ai = pk2(ra[i]);
                #pragma unroll
                for (int j = 0; j < 4; j++)
                    acc[i][j] = ffma2(ai, rb[j], acc[i][j]);
            }
        }
        __syncthreads();
    }

    #pragma unroll
    for (int i = 0; i < 8; i++) {
        const float* f = (const float*)acc[i];   // 4 u64 -> 8 floats, j-order
        const int m = m0 + trow*8 + i;
        #pragma unroll
        for (int j = 0; j < 8; j += 4) {
            const int n = n0 + tcol*8 + j;
            float4 o;
            o.x = alpha * (f[j+0] + bias[n+0]);
            o.y = alpha * (f[j+1] + bias[n+1]);
            o.z = alpha * (f[j+2] + bias[n+2]);
            o.w = alpha * (f[j+3] + bias[n+3]);
            *(float4*)(C + (size_t)m * N + n) = o;
        }
    }
}

// ============================================================================
// Local chunked relu-attention.
// Block = (window w, head h). out[64,64] = sum over chunks cw in {w-1,w,w+1}
// of relu(q_tile @ k_chunk^T) @ v_chunk.  Zero-padded chunks contribute 0
// exactly (relu(q.0)=0, v rows = 0), so out-of-range chunks are just skipped.
// Shared: qT (transposed, swizzled) + kT/v union + s — exactly 48KB.
// ============================================================================
#define SWZC(g,e) ((((g) ^ ((e) & 15)) << 2))

__global__ __launch_bounds__(256)
void local_attn(const float* __restrict__ Q, const float* __restrict__ Km,
                const float* __restrict__ Vm, float* __restrict__ O)
{
    __shared__ float qT[64][64];   // [e][i], float4-group swizzled by e
    __shared__ float kv[64][64];   // kT [e][j] swizzled in s-phase; v [j][e] plain in acc phase
    __shared__ float ss[64][64];   // relu(scores) [i][j]
    const int w   = blockIdx.x;
    const int h   = blockIdx.y;
    const int tid = threadIdx.x;
    const int tx  = tid & 15;      // j / e tile coord
    const int ty  = tid >> 4;      // i tile coord
    const int cb  = h * HD;

    // load q tile transposed: qT[e][i]
    #pragma unroll
    for (int l = 0; l < 4; l++) {
        int idx = tid + l * 256;
        int i   = idx >> 4;
        int e4  = (idx & 15) << 2;
        float4 t = *(const float4*)(Q + (size_t)(w*CH + i)*EDIM + cb + e4);
        int g = i >> 2, im = i & 3;
        qT[e4+0][SWZC(g, e4+0) + im] = t.x;
        qT[e4+1][SWZC(g, e4+1) + im] = t.y;
        qT[e4+2][SWZC(g, e4+2) + im] = t.z;
        qT[e4+3][SWZC(g, e4+3) + im] = t.w;
    }

    float o[4][4] = {};

    for (int cw = w - 1; cw <= w + 1; cw++) {
        if (cw < 0 || cw >= NW) continue;          // uniform per block
        __syncthreads();                           // prev-iter readers done; qT ready (1st)

        // load k chunk transposed+swizzled: kv[e][j]
        #pragma unroll
        for (int l = 0; l < 4; l++) {
            int idx = tid + l * 256;
            int j   = idx >> 4;
            int e4  = (idx & 15) << 2;
            float4 t = *(const float4*)(Km + (size_t)(cw*CH + j)*EDIM + cb + e4);
            int g = j >> 2, jm = j & 3;
            kv[e4+0][SWZC(g, e4+0) + jm] = t.x;
            kv[e4+1][SWZC(g, e4+1) + jm] = t.y;
            kv[e4+2][SWZC(g, e4+2) + jm] = t.z;
            kv[e4+3][SWZC(g, e4+3) + jm] = t.w;
        }
        __syncthreads();

        // s[i][j] = sum_e q[i][e] * k[j][e]
        float s[4][4] = {};
        #pragma unroll 8
        for (int e = 0; e < 64; e++) {
            float4 a = *(const float4*)&qT[e][SWZC(ty, e)];
            float4 b = *(const float4*)&kv[e][SWZC(tx, e)];
            float av[4] = {a.x, a.y, a.z, a.w};
            float bv[4] = {b.x, b.y, b.z, b.w};
            #pragma unroll
            for (int rr = 0; rr < 4; rr++)
                #pragma unroll
                for (int cc = 0; cc < 4; cc++)
                    s[rr][cc] += av[rr] * bv[cc];
        }
        #pragma unroll
        for (int rr = 0; rr < 4; rr++)
            #pragma unroll
            for (int cc = 0; cc < 4; cc++)
                ss[ty*4+rr][tx*4+cc] = fmaxf(s[rr][cc], 0.0f);
        __syncthreads();                           // ss ready; kT reads done

        // load v chunk plain: kv[j][e]
        #pragma unroll
        for (int l = 0; l < 4; l++) {
            int idx = tid + l * 256;
            int j   = idx >> 4;
            int e4  = (idx & 15) << 2;
            *(float4*)&kv[j][e4] =
                *(const float4*)(Vm + (size_t)(cw*CH + j)*EDIM + cb + e4);
        }
        __syncthreads();

        // o[i][e] += sum_j ss[i][j] * v[j][e]
        #pragma unroll 8
        for (int j = 0; j < 64; j++) {
            float4 vv = *(const float4*)&kv[j][tx*4];
            float s0 = ss[ty*4+0][j];
            float s1 = ss[ty*4+1][j];
            float s2 = ss[ty*4+2][j];
            float s3 = ss[ty*4+3][j];
            o[0][0] += s0*vv.x; o[0][1] += s0*vv.y; o[0][2] += s0*vv.z; o[0][3] += s0*vv.w;
            o[1][0] += s1*vv.x; o[1][1] += s1*vv.y; o[1][2] += s1*vv.z; o[1][3] += s1*vv.w;
            o[2][0] += s2*vv.x; o[2][1] += s2*vv.y; o[2][2] += s2*vv.z; o[2][3] += s2*vv.w;
            o[3][0] += s3*vv.x; o[3][1] += s3*vv.y; o[3][2] += s3*vv.z; o[3][3] += s3*vv.w;
        }
    }

    #pragma unroll
    for (int rr = 0; rr < 4; rr++) {
        float4 t = make_float4(o[rr][0], o[rr][1], o[rr][2], o[rr][3]);
        *(float4*)(O + (size_t)(w*CH + ty*4 + rr)*EDIM + cb + tx*4) = t;
    }
}

// ============================================================================
// Gated RMSNorm over E=1024: y = scale * (x / (rms + 1e-8)) * sigmoid(gate*x)
// One block per row, 256 threads, 1 float4 per thread.
// ============================================================================
__global__ __launch_bounds__(256)
void rms_gate(const float* __restrict__ X, const float* __restrict__ sc,
              const float* __restrict__ gt, float* __restrict__ Y)
{
    __shared__ float red[8];
    const int row = blockIdx.x;
    const int tid = threadIdx.x;
    float4 x = ((const float4*)(X + (size_t)row * EDIM))[tid];
    float ssq = x.x*x.x + x.y*x.y + x.z*x.z + x.w*x.w;
    #pragma unroll
    for (int d = 16; d; d >>= 1) ssq += __shfl_xor_sync(0xffffffffu, ssq, d);
    if ((tid & 31) == 0) red[tid >> 5] = ssq;
    __syncthreads();
    if (tid < 32) {
        float t = (tid < 8) ? red[tid] : 0.0f;
        #pragma unroll
        for (int d = 4; d; d >>= 1) t += __shfl_xor_sync(0xffffffffu, t, d);
        if (tid == 0) red[0] = t;
    }
    __syncthreads();
    const float rms = sqrtf(red[0] * (1.0f / EDIM));
    const float inv = 1.0f / (rms + 1e-8f);
    const int c = tid << 2;
    float4 s4 = *(const float4*)(sc + c);
    float4 g4 = *(const float4*)(gt + c);
    float4 y;
    y.x = s4.x * x.x * inv * (1.0f / (1.0f + __expf(-g4.x * x.x)));
    y.y = s4.y * x.y * inv * (1.0f / (1.0f + __expf(-g4.y * x.y)));
    y.z = s4.z * x.z * inv * (1.0f / (1.0f + __expf(-g4.z * x.z)));
    y.w = s4.w * x.w * inv * (1.0f / (1.0f + __expf(-g4.w * x.w)));
    ((float4*)(Y + (size_t)row * EDIM))[tid] = y;
}

// ============================================================================
extern "C" void kernel_launch(void* const* d_in, const int* in_sizes, int n_in,
                              void* d_out, int out_size)
{
    const float* query = (const float*)d_in[0];
    const float* key_  = (const float*)d_in[1];
    const float* value = (const float*)d_in[2];
    const float* w_q   = (const float*)d_in[3];
    const float* b_q   = (const float*)d_in[4];
    const float* w_k   = (const float*)d_in[5];
    const float* b_k   = (const float*)d_in[6];
    const float* w_v   = (const float*)d_in[7];
    const float* b_v   = (const float*)d_in[8];
    const float* w_o   = (const float*)d_in[9];
    const float* b_o   = (const float*)d_in[10];
    const float* nsc   = (const float*)d_in[11];
    const float* ngt   = (const float*)d_in[12];
    float* out = (float*)d_out;

    void *pq, *pk, *pv, *pa, *pn;
    cudaGetSymbolAddress(&pq, g_q);
    cudaGetSymbolAddress(&pk, g_k);
    cudaGetSymbolAddress(&pv, g_v);
    cudaGetSymbolAddress(&pa, g_att);
    cudaGetSymbolAddress(&pn, g_nrm);
    float* gq = (float*)pq;
    float* gk = (float*)pk;
    float* gv = (float*)pv;
    float* ga = (float*)pa;
    float* gn = (float*)pn;

    const dim3 ggrd(EDIM/128, LSEQ/128);   // (8, 64)
    const float scaling = 0.125f;          // HD^-0.5

    gemm_abt<<<ggrd, 256>>>(query, w_q, b_q, gq, LSEQ, EDIM, EDIM, scaling);
    gemm_abt<<<ggrd, 256>>>(key_,  w_k, b_k, gk, LSEQ, EDIM, EDIM, 1.0f);
    gemm_abt<<<ggrd, 256>>>(value, w_v, b_v, gv, LSEQ, EDIM, EDIM, 1.0f);

    local_attn<<<dim3(NW, NH), 256>>>(gq, gk, gv, ga);

    rms_gate<<<LSEQ, 256>>>(ga, nsc, ngt, gn);

    gemm_abt<<<ggrd, 256>>>(gn, w_o, b_o, out, LSEQ, EDIM, EDIM, 1.0f);
}